// round 11
// baseline (speedup 1.0000x reference)
#include <cuda_runtime.h>
#include <math.h>
#include <stdint.h>

#define HQn 16
#define HKn 4
#define Dn 64
#define GATE_CHn 12
#define WINDOWn 1024
#define Bn 2
#define Tn 2048
#define En 1024
#define Fn 1536
#define Mn 4096

// Scratch (allocation-free rule: device globals)
__device__ __align__(256) float g_qkv[(size_t)Mn * Fn];
__device__ __align__(256) float g_att[(size_t)Mn * En];
__device__ __align__(256) uint32_t g_qpack[(size_t)Bn * HQn * Tn * Dn];
__device__ __align__(256) uint32_t g_kpack[(size_t)Bn * HKn * Tn * Dn];
__device__ __align__(256) uint32_t g_vpack[(size_t)Bn * HKn * Tn * Dn];

// ---------------------------------------------------------------------------
// helpers
// ---------------------------------------------------------------------------
__device__ __forceinline__ uint32_t f2tf32(float x) {
    uint32_t r;
    asm("cvt.rna.tf32.f32 %0, %1;" : "=r"(r) : "f"(x));
    return r;
}

__device__ __forceinline__ void mma_tf32(float* d, const uint32_t* a,
                                         const uint32_t* b) {
    asm volatile(
        "mma.sync.aligned.m16n8k8.row.col.f32.tf32.tf32.f32 "
        "{%0,%1,%2,%3}, {%4,%5,%6,%7}, {%8,%9}, {%0,%1,%2,%3};\n"
        : "+f"(d[0]), "+f"(d[1]), "+f"(d[2]), "+f"(d[3])
        : "r"(a[0]), "r"(a[1]), "r"(a[2]), "r"(a[3]), "r"(b[0]), "r"(b[1]));
}

__device__ __forceinline__ uint32_t sma(const void* p) {
    return (uint32_t)__cvta_generic_to_shared(p);
}
__device__ __forceinline__ void cp16(uint32_t dst, const void* src) {
    asm volatile("cp.async.cg.shared.global [%0], [%1], 16;\n"
                 :: "r"(dst), "l"(src));
}
__device__ __forceinline__ void cp_commit() {
    asm volatile("cp.async.commit_group;\n");
}
template <int N>
__device__ __forceinline__ void cp_wait() {
    asm volatile("cp.async.wait_group %0;\n" :: "n"(N));
}

__device__ __forceinline__ int permd(int d) {     // 64-chunk k-run permute
    return (d & 3) * 16 + (d >> 2);
}

// ---------------------------------------------------------------------------
// TF32 GEMM (round-8 proven config): C[M,N] = A[M,K] * B[N,K]^T.
// cp.async double-buffered raw fp32 smem (stride 36, conflict-free scalar
// fragment loads), cvt to tf32 at fragment load. 128x128 tile, BK=32,
// 8 warps (warp: 32m x 64n).
// ---------------------------------------------------------------------------
#define GBUF_W (128 * 36)
#define GEMM_SMEM_BYTES (4 * GBUF_W * 4)

__global__ __launch_bounds__(256, 2) void gemm_tf32(
    const float* __restrict__ A, const float* __restrict__ Bm,
    float* __restrict__ C, int M, int N, int K)
{
    extern __shared__ float dynsm[];

    const int tid = threadIdx.x;
    const int lane = tid & 31;
    const int warp = tid >> 5;
    const int wm = (warp & 3) * 32;
    const int wn = (warp >> 2) * 64;
    const int bm = blockIdx.y * 128;
    const int bn = blockIdx.x * 128;
    const int lq = lane >> 2;
    const int lc = lane & 3;

    float acc[2][8][4];
    #pragma unroll
    for (int mt = 0; mt < 2; mt++)
        #pragma unroll
        for (int nt = 0; nt < 8; nt++)
            #pragma unroll
            for (int i = 0; i < 4; i++) acc[mt][nt][i] = 0.f;

    auto pref = [&](int b, int k0) {
        float* Ad = dynsm + b * (2 * GBUF_W);
        float* Bd = Ad + GBUF_W;
        #pragma unroll
        for (int i = 0; i < 4; i++) {
            const int g = tid + 256 * i;
            const int row = g >> 3;
            const int c4 = (g & 7) * 4;
            cp16(sma(Ad + row * 36 + c4), A + (size_t)(bm + row) * K + k0 + c4);
            cp16(sma(Bd + row * 36 + c4), Bm + (size_t)(bn + row) * K + k0 + c4);
        }
    };

    const int niter = K / 32;
    pref(0, 0);
    cp_commit();

    for (int ki = 0; ki < niter; ki++) {
        if (ki + 1 < niter) {
            pref((ki + 1) & 1, (ki + 1) * 32);
            cp_commit();
            cp_wait<1>();
        } else {
            cp_wait<0>();
        }
        __syncthreads();

        const float* Ac = dynsm + (ki & 1) * (2 * GBUF_W);
        const float* Bc = Ac + GBUF_W;

        uint32_t a_all[4][8];
        #pragma unroll
        for (int r = 0; r < 4; r++) {
            const float* p = Ac + (wm + lq + 8 * r) * 36 + lc;
            #pragma unroll
            for (int j = 0; j < 8; j++)
                a_all[r][j] = f2tf32(p[4 * j]);
        }

        #pragma unroll
        for (int nt = 0; nt < 8; nt++) {
            const float* p = Bc + (wn + nt * 8 + lq) * 36 + lc;
            uint32_t bbv[8];
            #pragma unroll
            for (int j = 0; j < 8; j++)
                bbv[j] = f2tf32(p[4 * j]);
            #pragma unroll
            for (int ks = 0; ks < 4; ks++) {
                uint32_t af0[4] = {a_all[0][2 * ks], a_all[1][2 * ks],
                                   a_all[0][2 * ks + 1], a_all[1][2 * ks + 1]};
                uint32_t af1[4] = {a_all[2][2 * ks], a_all[3][2 * ks],
                                   a_all[2][2 * ks + 1], a_all[3][2 * ks + 1]};
                uint32_t bf[2] = {bbv[2 * ks], bbv[2 * ks + 1]};
                mma_tf32(acc[0][nt], af0, bf);
                mma_tf32(acc[1][nt], af1, bf);
            }
        }
        __syncthreads();
    }

    #pragma unroll
    for (int mt = 0; mt < 2; mt++) {
        const int r0 = bm + wm + mt * 16 + lq;
        #pragma unroll
        for (int nt = 0; nt < 8; nt++) {
            const int c0 = bn + wn + nt * 8 + 2 * lc;
            *(float2*)(C + (size_t)r0 * N + c0) =
                make_float2(acc[mt][nt][0], acc[mt][nt][1]);
            *(float2*)(C + (size_t)(r0 + 8) * N + c0) =
                make_float2(acc[mt][nt][2], acc[mt][nt][3]);
        }
    }
}

// ---------------------------------------------------------------------------
// rope_rms_pack: gate + value_embeds mix, RoPE + RMSNorm, pre-convert to
// packed tf32: qpack (q*0.125, permd), kpack (permd), vpack (plain).
// ---------------------------------------------------------------------------
__global__ __launch_bounds__(128) void rope_rms_pack(
    const float* __restrict__ qkv, const float* __restrict__ x,
    const float* __restrict__ ve, const float* __restrict__ rc,
    const float* __restrict__ rs, const float* __restrict__ wg,
    uint32_t* __restrict__ qpack, uint32_t* __restrict__ kpack,
    uint32_t* __restrict__ vpack)
{
    const int row = blockIdx.x;
    const int t = row & (Tn - 1);
    const int b = row >> 11;
    const int warp = threadIdx.x >> 5;
    const int lane = threadIdx.x & 31;

    for (int head = warp; head < HQn + 2 * HKn; head += 4) {
        const float* p = qkv + (size_t)row * Fn + head * Dn;
        if (head < HQn + HKn) {
            float x1 = p[lane], x2 = p[lane + 32];
            float c = rc[t * (Dn / 2) + lane];
            float s = rs[t * (Dn / 2) + lane];
            float y1 = x1 * c - x2 * s;
            float y2 = x1 * s + x2 * c;
            float ss = y1 * y1 + y2 * y2;
            #pragma unroll
            for (int o = 16; o; o >>= 1) ss += __shfl_xor_sync(0xffffffffu, ss, o);
            float r = rsqrtf(ss * (1.0f / Dn) + 1e-8f);
            y1 *= r; y2 *= r;
            if (head < HQn) {
                uint32_t* qp = qpack + ((size_t)(b * HQn + head) * Tn + t) * Dn;
                qp[permd(lane)]      = f2tf32(y1 * 0.125f);
                qp[permd(lane + 32)] = f2tf32(y2 * 0.125f);
            } else {
                const int hk = head - HQn;
                uint32_t* kp = kpack + ((size_t)(b * HKn + hk) * Tn + t) * Dn;
                kp[permd(lane)]      = f2tf32(y1);
                kp[permd(lane + 32)] = f2tf32(y2);
            }
        } else {
            const int hv = head - HQn - HKn;
            float pr = (lane < GATE_CHn)
                         ? x[(size_t)row * En + lane] * wg[hv * GATE_CHn + lane]
                         : 0.f;
            #pragma unroll
            for (int o = 16; o; o >>= 1) pr += __shfl_xor_sync(0xffffffffu, pr, o);
            float gate = 3.0f / (1.0f + __expf(-pr));
            const float* vp = ve + (size_t)row * (HKn * Dn) + hv * Dn;
            uint32_t* vd = vpack + ((size_t)(b * HKn + hv) * Tn + t) * Dn;
            vd[lane]      = f2tf32(p[lane]      + gate * vp[lane]);
            vd[lane + 32] = f2tf32(p[lane + 32] + gate * vp[lane + 32]);
        }
    }
}

// ---------------------------------------------------------------------------
// Tensor-core flash attention (round-9 proven config): single-tf32 S,
// pre-converted operands, zero cvt in mainloop, KTILE=32 cp.async
// double-buffered. Output stored as plain fp32 (consumed by gemm_tf32).
// ---------------------------------------------------------------------------
#define QTILE 128
#define KTILE 32
#define AK_W (32 * 68)
#define AV_W (32 * 72)
#define ABUF_W (AK_W + AV_W)
#define W_PS2 (2 * ABUF_W)
#define ATTN_WORDS (W_PS2 + QTILE * 36)
#define ATTN_SMEM_BYTES (ATTN_WORDS * 4)

__global__ __launch_bounds__(256, 2) void attn_tc(
    const uint32_t* __restrict__ qpack, const uint32_t* __restrict__ kpack,
    const uint32_t* __restrict__ vpack, float* __restrict__ out)
{
    extern __shared__ uint32_t smu[];
    uint32_t* Ps = smu + W_PS2;

    const int tid = threadIdx.x;
    const int lane = tid & 31;
    const int warp = tid >> 5;
    const int q0 = blockIdx.x * QTILE;
    const int h  = blockIdx.y;
    const int bb = blockIdx.z;
    const int hk = h >> 2;
    const int row0 = bb * Tn + q0;

    const int lq = lane >> 2;
    const int lc = lane & 3;
    const int rA = warp * 16 + lq;

    const uint32_t* kp_base = kpack + (size_t)(bb * HKn + hk) * Tn * Dn;
    const uint32_t* vp_base = vpack + (size_t)(bb * HKn + hk) * Tn * Dn;

    uint32_t qA[16], qB[16];
    {
        const uint32_t* qp0 = qpack +
            ((size_t)(bb * HQn + h) * Tn + q0 + rA) * Dn + lc * 16;
        const uint32_t* qp1 = qp0 + 8 * Dn;
        #pragma unroll
        for (int u = 0; u < 4; u++) {
            *(uint4*)&qA[4 * u] = *(const uint4*)(qp0 + 4 * u);
            *(uint4*)&qB[4 * u] = *(const uint4*)(qp1 + 4 * u);
        }
    }

    float o[8][4];
    #pragma unroll
    for (int nt = 0; nt < 8; nt++)
        #pragma unroll
        for (int e = 0; e < 4; e++) o[nt][e] = 0.f;
    float lA = 0.f, lB = 0.f;

    const int kt_lo = (q0 > WINDOWn) ? ((q0 - WINDOWn) >> 5) : 0;
    const int kt_hi = (q0 + QTILE - 1) >> 5;

    auto pref = [&](int bidx, int kt) {
        const int kbase = kt * KTILE;
        uint32_t* Kd = smu + bidx * ABUF_W;
        uint32_t* Vd = Kd + AK_W;
        #pragma unroll
        for (int i = 0; i < 4; i++) {
            const int g = tid + 256 * i;
            const int reg = g >> 9;
            const int idx = g & 511;
            const int row = idx >> 4;
            const int c4 = (idx & 15) * 4;
            if (reg == 0)
                cp16(sma(Kd + row * 68 + c4),
                     kp_base + (size_t)(kbase + row) * Dn + c4);
            else
                cp16(sma(Vd + row * 72 + c4),
                     vp_base + (size_t)(kbase + row) * Dn + c4);
        }
    };

    pref(0, kt_lo);
    cp_commit();

    for (int kt = kt_lo; kt <= kt_hi; kt++) {
        const int cur = (kt - kt_lo) & 1;
        if (kt < kt_hi) {
            pref(cur ^ 1, kt + 1);
            cp_commit();
            cp_wait<1>();
        } else {
            cp_wait<0>();
        }
        __syncthreads();

        const uint32_t* Khi = smu + cur * ABUF_W;
        const uint32_t* Vv  = Khi + AK_W;
        const int k0 = kt * KTILE;
        const int swP = (warp * 2) & 3;

        #pragma unroll
        for (int nt = 0; nt < 4; nt++) {
            const int key = nt * 8 + lq;
            const uint32_t* ph = Khi + key * 68 + lc * 16;
            uint32_t kh[16];
            #pragma unroll
            for (int u = 0; u < 4; u++)
                *(uint4*)&kh[4 * u] = *(const uint4*)(ph + 4 * u);

            float s0[4] = {0.f, 0.f, 0.f, 0.f};
            float s1[4] = {0.f, 0.f, 0.f, 0.f};
            #pragma unroll
            for (int kp2 = 0; kp2 < 4; kp2++) {
                const int ka = 2 * kp2, kb = 2 * kp2 + 1;
                uint32_t afa[4] = {qA[2 * ka], qB[2 * ka],
                                   qA[2 * ka + 1], qB[2 * ka + 1]};
                uint32_t afb[4] = {qA[2 * kb], qB[2 * kb],
                                   qA[2 * kb + 1], qB[2 * kb + 1]};
                uint32_t bha[2] = {kh[2 * ka], kh[2 * ka + 1]};
                uint32_t bhb[2] = {kh[2 * kb], kh[2 * kb + 1]};
                mma_tf32(s0, afa, bha);
                mma_tf32(s1, afb, bhb);
            }

            float p[4];
            #pragma unroll
            for (int e = 0; e < 4; e++) {
                const float sv = s0[e] + s1[e];
                const int i = q0 + rA + ((e >= 2) ? 8 : 0);
                const int j = k0 + nt * 8 + 2 * lc + (e & 1);
                const bool live = (j <= i) && (j + WINDOWn >= i);
                p[e] = live ? __expf(sv - 8.0f) : 0.f;
            }
            lA += p[0] + p[1];
            lB += p[2] + p[3];

            #pragma unroll
            for (int e = 0; e < 4; e++) {
                const int col = nt * 8 + 2 * lc + (e & 1);
                const int row = rA + ((e >= 2) ? 8 : 0);
                Ps[row * 36 + (((col & 3) ^ swP) << 3) + (col >> 2)] =
                    f2tf32(p[e]);
            }
        }
        __syncwarp();

        uint32_t pA[8], pB[8];
        {
            const uint32_t* p0 = &Ps[rA * 36 + ((lc ^ swP) << 3)];
            const uint32_t* p1 = &Ps[(rA + 8) * 36 + ((lc ^ swP) << 3)];
            *(uint4*)&pA[0] = *(const uint4*)p0;
            *(uint4*)&pA[4] = *(const uint4*)(p0 + 4);
            *(uint4*)&pB[0] = *(const uint4*)p1;
            *(uint4*)&pB[4] = *(const uint4*)(p1 + 4);
        }
        #pragma unroll
        for (int ks = 0; ks < 4; ks++) {
            const int kp = ks * 8 + lc;
            uint32_t af[4] = {pA[2 * ks], pB[2 * ks],
                              pA[2 * ks + 1], pB[2 * ks + 1]};
            #pragma unroll
            for (int nt = 0; nt < 8; nt++) {
                const int d = nt * 8 + lq;
                uint32_t bf[2] = {Vv[kp * 72 + d], Vv[(kp + 4) * 72 + d]};
                mma_tf32(o[nt], af, bf);
            }
        }
        __syncthreads();
    }

    lA += __shfl_xor_sync(0xffffffffu, lA, 1);
    lA += __shfl_xor_sync(0xffffffffu, lA, 2);
    lB += __shfl_xor_sync(0xffffffffu, lB, 1);
    lB += __shfl_xor_sync(0xffffffffu, lB, 2);
    const float invA = 1.0f / lA;
    const float invB = 1.0f / lB;

    // plain fp32 output (gemm_tf32 converts at its own fragment load)
    #pragma unroll
    for (int nt = 0; nt < 8; nt++) {
        const int c0 = h * Dn + nt * 8 + 2 * lc;
        *(float2*)(out + (size_t)(row0 + rA) * En + c0) =
            make_float2(o[nt][0] * invA, o[nt][1] * invA);
        *(float2*)(out + (size_t)(row0 + rA + 8) * En + c0) =
            make_float2(o[nt][2] * invB, o[nt][3] * invB);
    }
}

// ---------------------------------------------------------------------------
extern "C" void kernel_launch(void* const* d_in, const int* in_sizes, int n_in,
                              void* d_out, int out_size)
{
    (void)in_sizes; (void)n_in; (void)out_size;
    const float* x    = (const float*)d_in[0];
    const float* ve   = (const float*)d_in[1];
    const float* rc   = (const float*)d_in[2];
    const float* rs   = (const float*)d_in[3];
    const float* wqkv = (const float*)d_in[4];
    const float* wg   = (const float*)d_in[5];
    const float* wo   = (const float*)d_in[6];
    float* out = (float*)d_out;

    float *qkv_p = nullptr, *att_p = nullptr;
    uint32_t *qp = nullptr, *kp = nullptr, *vp = nullptr;
    cudaGetSymbolAddress((void**)&qkv_p, g_qkv);
    cudaGetSymbolAddress((void**)&att_p, g_att);
    cudaGetSymbolAddress((void**)&qp, g_qpack);
    cudaGetSymbolAddress((void**)&kp, g_kpack);
    cudaGetSymbolAddress((void**)&vp, g_vpack);

    cudaFuncSetAttribute(gemm_tf32,
                         cudaFuncAttributeMaxDynamicSharedMemorySize,
                         GEMM_SMEM_BYTES);
    cudaFuncSetAttribute(attn_tc,
                         cudaFuncAttributeMaxDynamicSharedMemorySize,
                         ATTN_SMEM_BYTES);

    gemm_tf32<<<dim3(Fn / 128, Mn / 128), 256, GEMM_SMEM_BYTES>>>(
        x, wqkv, qkv_p, Mn, Fn, En);
    rope_rms_pack<<<Mn, 128>>>(qkv_p, x, ve, rc, rs, wg, qp, kp, vp);
    attn_tc<<<dim3(Tn / QTILE, HQn, Bn), 256, ATTN_SMEM_BYTES>>>(
        qp, kp, vp, att_p);
    gemm_tf32<<<dim3(En / 128, Mn / 128), 256, GEMM_SMEM_BYTES>>>(
        att_p, wo, out, Mn, En, En);
}

// round 12
// speedup vs baseline: 1.5338x; 1.5338x over previous
#include <cuda_runtime.h>
#include <math.h>
#include <stdint.h>

#define HQn 16
#define HKn 4
#define Dn 64
#define GATE_CHn 12
#define WINDOWn 1024
#define Bn 2
#define Tn 2048
#define En 1024
#define Fn 1536
#define Mn 4096

// Scratch (allocation-free rule: device globals)
__device__ __align__(256) float g_qkv[(size_t)Mn * Fn];
__device__ __align__(256) float g_att[(size_t)Mn * En];
__device__ __align__(256) uint32_t g_qpack[(size_t)Bn * HQn * Tn * Dn];
__device__ __align__(256) uint32_t g_kpack[(size_t)Bn * HKn * Tn * Dn];
__device__ __align__(256) uint32_t g_vpack[(size_t)Bn * HKn * Tn * Dn];

// ---------------------------------------------------------------------------
// helpers
// ---------------------------------------------------------------------------
__device__ __forceinline__ uint32_t f2tf32(float x) {
    uint32_t r;
    asm("cvt.rna.tf32.f32 %0, %1;" : "=r"(r) : "f"(x));
    return r;
}

__device__ __forceinline__ void mma_tf32(float* d, const uint32_t* a,
                                         const uint32_t* b) {
    asm volatile(
        "mma.sync.aligned.m16n8k8.row.col.f32.tf32.tf32.f32 "
        "{%0,%1,%2,%3}, {%4,%5,%6,%7}, {%8,%9}, {%0,%1,%2,%3};\n"
        : "+f"(d[0]), "+f"(d[1]), "+f"(d[2]), "+f"(d[3])
        : "r"(a[0]), "r"(a[1]), "r"(a[2]), "r"(a[3]), "r"(b[0]), "r"(b[1]));
}

__device__ __forceinline__ uint32_t sma(const void* p) {
    return (uint32_t)__cvta_generic_to_shared(p);
}
__device__ __forceinline__ void cp16(uint32_t dst, const void* src) {
    asm volatile("cp.async.cg.shared.global [%0], [%1], 16;\n"
                 :: "r"(dst), "l"(src));
}
__device__ __forceinline__ void cp_commit() {
    asm volatile("cp.async.commit_group;\n");
}
template <int N>
__device__ __forceinline__ void cp_wait() {
    asm volatile("cp.async.wait_group %0;\n" :: "n"(N));
}

__device__ __forceinline__ int permd(int d) {     // 64-chunk k-run permute
    return (d & 3) * 16 + (d >> 2);
}

// ---------------------------------------------------------------------------
// TF32 GEMM: C[M,N] = A[M,K] * B[N,K]^T. cp.async double-buffered raw fp32
// smem (stride 36, conflict-free scalar fragment loads), cvt at fragment
// load. 128x128 tile, BK=32, 8 warps (warp 32m x 64n).
// MMA ordering: nt-pair groups, ks-outer -> same-accumulator reuse
// distance 4 (hides HMMA latency with 4 warps/SMSP).
// ---------------------------------------------------------------------------
#define GBUF_W (128 * 36)
#define GEMM_SMEM_BYTES (4 * GBUF_W * 4)

__global__ __launch_bounds__(256, 2) void gemm_tf32(
    const float* __restrict__ A, const float* __restrict__ Bm,
    float* __restrict__ C, int M, int N, int K)
{
    extern __shared__ float dynsm[];

    const int tid = threadIdx.x;
    const int lane = tid & 31;
    const int warp = tid >> 5;
    const int wm = (warp & 3) * 32;
    const int wn = (warp >> 2) * 64;
    const int bm = blockIdx.y * 128;
    const int bn = blockIdx.x * 128;
    const int lq = lane >> 2;
    const int lc = lane & 3;

    float acc[2][8][4];
    #pragma unroll
    for (int mt = 0; mt < 2; mt++)
        #pragma unroll
        for (int nt = 0; nt < 8; nt++)
            #pragma unroll
            for (int i = 0; i < 4; i++) acc[mt][nt][i] = 0.f;

    auto pref = [&](int b, int k0) {
        float* Ad = dynsm + b * (2 * GBUF_W);
        float* Bd = Ad + GBUF_W;
        #pragma unroll
        for (int i = 0; i < 4; i++) {
            const int g = tid + 256 * i;
            const int row = g >> 3;
            const int c4 = (g & 7) * 4;
            cp16(sma(Ad + row * 36 + c4), A + (size_t)(bm + row) * K + k0 + c4);
            cp16(sma(Bd + row * 36 + c4), Bm + (size_t)(bn + row) * K + k0 + c4);
        }
    };

    const int niter = K / 32;
    pref(0, 0);
    cp_commit();

    for (int ki = 0; ki < niter; ki++) {
        if (ki + 1 < niter) {
            pref((ki + 1) & 1, (ki + 1) * 32);
            cp_commit();
            cp_wait<1>();
        } else {
            cp_wait<0>();
        }
        __syncthreads();

        const float* Ac = dynsm + (ki & 1) * (2 * GBUF_W);
        const float* Bc = Ac + GBUF_W;

        uint32_t a_all[4][8];
        #pragma unroll
        for (int r = 0; r < 4; r++) {
            const float* p = Ac + (wm + lq + 8 * r) * 36 + lc;
            #pragma unroll
            for (int j = 0; j < 8; j++)
                a_all[r][j] = f2tf32(p[4 * j]);
        }

        #pragma unroll
        for (int g = 0; g < 4; g++) {
            uint32_t bb[2][8];
            #pragma unroll
            for (int j = 0; j < 2; j++) {
                const float* p = Bc + (wn + (g * 2 + j) * 8 + lq) * 36 + lc;
                #pragma unroll
                for (int w = 0; w < 8; w++)
                    bb[j][w] = f2tf32(p[4 * w]);
            }
            // ks-outer over the nt pair: same-acc reuse distance = 4 MMAs
            #pragma unroll
            for (int ks = 0; ks < 4; ks++) {
                uint32_t af0[4] = {a_all[0][2 * ks], a_all[1][2 * ks],
                                   a_all[0][2 * ks + 1], a_all[1][2 * ks + 1]};
                uint32_t af1[4] = {a_all[2][2 * ks], a_all[3][2 * ks],
                                   a_all[2][2 * ks + 1], a_all[3][2 * ks + 1]};
                #pragma unroll
                for (int j = 0; j < 2; j++) {
                    const int nt = g * 2 + j;
                    uint32_t bf[2] = {bb[j][2 * ks], bb[j][2 * ks + 1]};
                    mma_tf32(acc[0][nt], af0, bf);
                    mma_tf32(acc[1][nt], af1, bf);
                }
            }
        }
        __syncthreads();
    }

    #pragma unroll
    for (int mt = 0; mt < 2; mt++) {
        const int r0 = bm + wm + mt * 16 + lq;
        #pragma unroll
        for (int nt = 0; nt < 8; nt++) {
            const int c0 = bn + wn + nt * 8 + 2 * lc;
            *(float2*)(C + (size_t)r0 * N + c0) =
                make_float2(acc[mt][nt][0], acc[mt][nt][1]);
            *(float2*)(C + (size_t)(r0 + 8) * N + c0) =
                make_float2(acc[mt][nt][2], acc[mt][nt][3]);
        }
    }
}

// ---------------------------------------------------------------------------
// rope_rms_pack: gate + value_embeds mix, RoPE + RMSNorm, pre-convert to
// packed tf32: qpack (q*0.125, permd), kpack (permd), vpack (plain).
// ---------------------------------------------------------------------------
__global__ __launch_bounds__(128) void rope_rms_pack(
    const float* __restrict__ qkv, const float* __restrict__ x,
    const float* __restrict__ ve, const float* __restrict__ rc,
    const float* __restrict__ rs, const float* __restrict__ wg,
    uint32_t* __restrict__ qpack, uint32_t* __restrict__ kpack,
    uint32_t* __restrict__ vpack)
{
    const int row = blockIdx.x;
    const int t = row & (Tn - 1);
    const int b = row >> 11;
    const int warp = threadIdx.x >> 5;
    const int lane = threadIdx.x & 31;

    for (int head = warp; head < HQn + 2 * HKn; head += 4) {
        const float* p = qkv + (size_t)row * Fn + head * Dn;
        if (head < HQn + HKn) {
            float x1 = p[lane], x2 = p[lane + 32];
            float c = rc[t * (Dn / 2) + lane];
            float s = rs[t * (Dn / 2) + lane];
            float y1 = x1 * c - x2 * s;
            float y2 = x1 * s + x2 * c;
            float ss = y1 * y1 + y2 * y2;
            #pragma unroll
            for (int o = 16; o; o >>= 1) ss += __shfl_xor_sync(0xffffffffu, ss, o);
            float r = rsqrtf(ss * (1.0f / Dn) + 1e-8f);
            y1 *= r; y2 *= r;
            if (head < HQn) {
                uint32_t* qp = qpack + ((size_t)(b * HQn + head) * Tn + t) * Dn;
                qp[permd(lane)]      = f2tf32(y1 * 0.125f);
                qp[permd(lane + 32)] = f2tf32(y2 * 0.125f);
            } else {
                const int hk = head - HQn;
                uint32_t* kp = kpack + ((size_t)(b * HKn + hk) * Tn + t) * Dn;
                kp[permd(lane)]      = f2tf32(y1);
                kp[permd(lane + 32)] = f2tf32(y2);
            }
        } else {
            const int hv = head - HQn - HKn;
            float pr = (lane < GATE_CHn)
                         ? x[(size_t)row * En + lane] * wg[hv * GATE_CHn + lane]
                         : 0.f;
            #pragma unroll
            for (int o = 16; o; o >>= 1) pr += __shfl_xor_sync(0xffffffffu, pr, o);
            float gate = 3.0f / (1.0f + __expf(-pr));
            const float* vp = ve + (size_t)row * (HKn * Dn) + hv * Dn;
            uint32_t* vd = vpack + ((size_t)(b * HKn + hv) * Tn + t) * Dn;
            vd[lane]      = f2tf32(p[lane]      + gate * vp[lane]);
            vd[lane + 32] = f2tf32(p[lane + 32] + gate * vp[lane + 32]);
        }
    }
}

// ---------------------------------------------------------------------------
// Tensor-core flash attention: single-tf32 S with 4 accumulator chains
// (distance 4), pre-converted operands, zero cvt in mainloop, KTILE=32
// cp.async double-buffered. Output plain fp32.
// ---------------------------------------------------------------------------
#define QTILE 128
#define KTILE 32
#define AK_W (32 * 68)
#define AV_W (32 * 72)
#define ABUF_W (AK_W + AV_W)
#define W_PS2 (2 * ABUF_W)
#define ATTN_WORDS (W_PS2 + QTILE * 36)
#define ATTN_SMEM_BYTES (ATTN_WORDS * 4)

__global__ __launch_bounds__(256, 2) void attn_tc(
    const uint32_t* __restrict__ qpack, const uint32_t* __restrict__ kpack,
    const uint32_t* __restrict__ vpack, float* __restrict__ out)
{
    extern __shared__ uint32_t smu[];
    uint32_t* Ps = smu + W_PS2;

    const int tid = threadIdx.x;
    const int lane = tid & 31;
    const int warp = tid >> 5;
    const int q0 = blockIdx.x * QTILE;
    const int h  = blockIdx.y;
    const int bb = blockIdx.z;
    const int hk = h >> 2;
    const int row0 = bb * Tn + q0;

    const int lq = lane >> 2;
    const int lc = lane & 3;
    const int rA = warp * 16 + lq;

    const uint32_t* kp_base = kpack + (size_t)(bb * HKn + hk) * Tn * Dn;
    const uint32_t* vp_base = vpack + (size_t)(bb * HKn + hk) * Tn * Dn;

    uint32_t qA[16], qB[16];
    {
        const uint32_t* qp0 = qpack +
            ((size_t)(bb * HQn + h) * Tn + q0 + rA) * Dn + lc * 16;
        const uint32_t* qp1 = qp0 + 8 * Dn;
        #pragma unroll
        for (int u = 0; u < 4; u++) {
            *(uint4*)&qA[4 * u] = *(const uint4*)(qp0 + 4 * u);
            *(uint4*)&qB[4 * u] = *(const uint4*)(qp1 + 4 * u);
        }
    }

    float o[8][4];
    #pragma unroll
    for (int nt = 0; nt < 8; nt++)
        #pragma unroll
        for (int e = 0; e < 4; e++) o[nt][e] = 0.f;
    float lA = 0.f, lB = 0.f;

    const int kt_lo = (q0 > WINDOWn) ? ((q0 - WINDOWn) >> 5) : 0;
    const int kt_hi = (q0 + QTILE - 1) >> 5;

    auto pref = [&](int bidx, int kt) {
        const int kbase = kt * KTILE;
        uint32_t* Kd = smu + bidx * ABUF_W;
        uint32_t* Vd = Kd + AK_W;
        #pragma unroll
        for (int i = 0; i < 4; i++) {
            const int g = tid + 256 * i;
            const int reg = g >> 9;
            const int idx = g & 511;
            const int row = idx >> 4;
            const int c4 = (idx & 15) * 4;
            if (reg == 0)
                cp16(sma(Kd + row * 68 + c4),
                     kp_base + (size_t)(kbase + row) * Dn + c4);
            else
                cp16(sma(Vd + row * 72 + c4),
                     vp_base + (size_t)(kbase + row) * Dn + c4);
        }
    };

    pref(0, kt_lo);
    cp_commit();

    for (int kt = kt_lo; kt <= kt_hi; kt++) {
        const int cur = (kt - kt_lo) & 1;
        if (kt < kt_hi) {
            pref(cur ^ 1, kt + 1);
            cp_commit();
            cp_wait<1>();
        } else {
            cp_wait<0>();
        }
        __syncthreads();

        const uint32_t* Khi = smu + cur * ABUF_W;
        const uint32_t* Vv  = Khi + AK_W;
        const int k0 = kt * KTILE;
        const int swP = (warp * 2) & 3;

        #pragma unroll
        for (int nt = 0; nt < 4; nt++) {
            const int key = nt * 8 + lq;
            const uint32_t* ph = Khi + key * 68 + lc * 16;
            uint32_t kh[16];
            #pragma unroll
            for (int u = 0; u < 4; u++)
                *(uint4*)&kh[4 * u] = *(const uint4*)(ph + 4 * u);

            // 4 independent accumulator chains (distance 4, depth 2)
            float s0[4] = {0.f, 0.f, 0.f, 0.f};
            float s1[4] = {0.f, 0.f, 0.f, 0.f};
            float s2[4] = {0.f, 0.f, 0.f, 0.f};
            float s3[4] = {0.f, 0.f, 0.f, 0.f};
            #pragma unroll
            for (int kp2 = 0; kp2 < 2; kp2++) {
                const int kb = 4 * kp2;
                #pragma unroll
                for (int c = 0; c < 4; c++) {
                    const int ks = kb + c;
                    uint32_t af[4] = {qA[2 * ks], qB[2 * ks],
                                      qA[2 * ks + 1], qB[2 * ks + 1]};
                    uint32_t bf[2] = {kh[2 * ks], kh[2 * ks + 1]};
                    float* sx = (c == 0) ? s0 : (c == 1) ? s1
                              : (c == 2) ? s2 : s3;
                    mma_tf32(sx, af, bf);
                }
            }

            float p[4];
            #pragma unroll
            for (int e = 0; e < 4; e++) {
                const float sv = (s0[e] + s1[e]) + (s2[e] + s3[e]);
                const int i = q0 + rA + ((e >= 2) ? 8 : 0);
                const int j = k0 + nt * 8 + 2 * lc + (e & 1);
                const bool live = (j <= i) && (j + WINDOWn >= i);
                p[e] = live ? __expf(sv - 8.0f) : 0.f;
            }
            lA += p[0] + p[1];
            lB += p[2] + p[3];

            #pragma unroll
            for (int e = 0; e < 4; e++) {
                const int col = nt * 8 + 2 * lc + (e & 1);
                const int row = rA + ((e >= 2) ? 8 : 0);
                Ps[row * 36 + (((col & 3) ^ swP) << 3) + (col >> 2)] =
                    f2tf32(p[e]);
            }
        }
        __syncwarp();

        uint32_t pA[8], pB[8];
        {
            const uint32_t* p0 = &Ps[rA * 36 + ((lc ^ swP) << 3)];
            const uint32_t* p1 = &Ps[(rA + 8) * 36 + ((lc ^ swP) << 3)];
            *(uint4*)&pA[0] = *(const uint4*)p0;
            *(uint4*)&pA[4] = *(const uint4*)(p0 + 4);
            *(uint4*)&pB[0] = *(const uint4*)p1;
            *(uint4*)&pB[4] = *(const uint4*)(p1 + 4);
        }
        #pragma unroll
        for (int ks = 0; ks < 4; ks++) {
            const int kp = ks * 8 + lc;
            uint32_t af[4] = {pA[2 * ks], pB[2 * ks],
                              pA[2 * ks + 1], pB[2 * ks + 1]};
            #pragma unroll
            for (int nt = 0; nt < 8; nt++) {
                const int d = nt * 8 + lq;
                uint32_t bf[2] = {Vv[kp * 72 + d], Vv[(kp + 4) * 72 + d]};
                mma_tf32(o[nt], af, bf);
            }
        }
        __syncthreads();
    }

    lA += __shfl_xor_sync(0xffffffffu, lA, 1);
    lA += __shfl_xor_sync(0xffffffffu, lA, 2);
    lB += __shfl_xor_sync(0xffffffffu, lB, 1);
    lB += __shfl_xor_sync(0xffffffffu, lB, 2);
    const float invA = 1.0f / lA;
    const float invB = 1.0f / lB;

    #pragma unroll
    for (int nt = 0; nt < 8; nt++) {
        const int c0 = h * Dn + nt * 8 + 2 * lc;
        *(float2*)(out + (size_t)(row0 + rA) * En + c0) =
            make_float2(o[nt][0] * invA, o[nt][1] * invA);
        *(float2*)(out + (size_t)(row0 + rA + 8) * En + c0) =
            make_float2(o[nt][2] * invB, o[nt][3] * invB);
    }
}

// ---------------------------------------------------------------------------
extern "C" void kernel_launch(void* const* d_in, const int* in_sizes, int n_in,
                              void* d_out, int out_size)
{
    (void)in_sizes; (void)n_in; (void)out_size;
    const float* x    = (const float*)d_in[0];
    const float* ve   = (const float*)d_in[1];
    const float* rc   = (const float*)d_in[2];
    const float* rs   = (const float*)d_in[3];
    const float* wqkv = (const float*)d_in[4];
    const float* wg   = (const float*)d_in[5];
    const float* wo   = (const float*)d_in[6];
    float* out = (float*)d_out;

    float *qkv_p = nullptr, *att_p = nullptr;
    uint32_t *qp = nullptr, *kp = nullptr, *vp = nullptr;
    cudaGetSymbolAddress((void**)&qkv_p, g_qkv);
    cudaGetSymbolAddress((void**)&att_p, g_att);
    cudaGetSymbolAddress((void**)&qp, g_qpack);
    cudaGetSymbolAddress((void**)&kp, g_kpack);
    cudaGetSymbolAddress((void**)&vp, g_vpack);

    cudaFuncSetAttribute(gemm_tf32,
                         cudaFuncAttributeMaxDynamicSharedMemorySize,
                         GEMM_SMEM_BYTES);
    cudaFuncSetAttribute(attn_tc,
                         cudaFuncAttributeMaxDynamicSharedMemorySize,
                         ATTN_SMEM_BYTES);

    gemm_tf32<<<dim3(Fn / 128, Mn / 128), 256, GEMM_SMEM_BYTES>>>(
        x, wqkv, qkv_p, Mn, Fn, En);
    rope_rms_pack<<<Mn, 128>>>(qkv_p, x, ve, rc, rs, wg, qp, kp, vp);
    attn_tc<<<dim3(Tn / QTILE, HQn, Bn), 256, ATTN_SMEM_BYTES>>>(
        qp, kp, vp, att_p);
    gemm_tf32<<<dim3(En / 128, Mn / 128), 256, GEMM_SMEM_BYTES>>>(
        att_p, wo, out, Mn, En, En);
}